// round 16
// baseline (speedup 1.0000x reference)
#include <cuda_runtime.h>
#include <cuda_fp16.h>
#include <stdint.h>
#include <math.h>

#define BATCH   8
#define NSEQ    1024
#define DIM     1024
#define HEADS   16
#define DHEAD   64
#define INNER   1024
#define ROWS    (BATCH*NSEQ)   // 8192
#define QKVW    (3*INNER)      // 3072

// Scratch (device globals: allocation-free per harness rules)
__device__ __half g_xn   [ROWS*DIM];     // fp16 LN output
__device__ __half g_qkv  [ROWS*QKVW];    // fp16 QKV
__device__ __half g_att  [ROWS*INNER];   // fp16 attention output
__device__ __half g_wqkvT[QKVW*DIM];     // W_qkv^T fp16 [n][k]
__device__ __half g_woutT[DIM*INNER];    // W_out^T fp16 [n][k]

#define LDMX4(r0,r1,r2,r3,addr)                                              \
    asm volatile("ldmatrix.sync.aligned.m8n8.x4.shared.b16 "                 \
                 "{%0,%1,%2,%3}, [%4];"                                      \
                 : "=r"(r0), "=r"(r1), "=r"(r2), "=r"(r3) : "r"(addr))

#define LDMX4T(r0,r1,r2,r3,addr)                                             \
    asm volatile("ldmatrix.sync.aligned.m8n8.x4.trans.shared.b16 "           \
                 "{%0,%1,%2,%3}, [%4];"                                      \
                 : "=r"(r0), "=r"(r1), "=r"(r2), "=r"(r3) : "r"(addr))

#define MMA_F16(c0,c1,c2,c3,a0,a1,a2,a3,b0,b1)                               \
    asm volatile(                                                            \
        "mma.sync.aligned.m16n8k16.row.col.f32.f16.f16.f32 "                 \
        "{%0,%1,%2,%3},{%4,%5,%6,%7},{%8,%9},{%0,%1,%2,%3};"                 \
        : "+f"(c0), "+f"(c1), "+f"(c2), "+f"(c3)                             \
        : "r"(a0), "r"(a1), "r"(a2), "r"(a3), "r"(b0), "r"(b1))

#define CPA(dst, src)                                                        \
    asm volatile("cp.async.cg.shared.global [%0], [%1], 16;"                 \
                 :: "r"(dst), "l"(src))

// ex2 on packed fp16x2: one MUFU op for two values.
__device__ __forceinline__ unsigned ex2_f16x2(float a, float b) {
    __half2 h = __floats2half2_rn(a, b);
    unsigned hi = *reinterpret_cast<unsigned*>(&h);
    unsigned r;
    asm volatile("ex2.approx.f16x2 %0, %1;" : "=r"(r) : "r"(hi));
    return r;
}

#define LOG2E 1.44269504088896f

// ---------------------------------------------------------------------------
// Weight transpose + fp16 convert: out[n*K + k] = half(in[k*N + n]).
// ---------------------------------------------------------------------------
__global__ __launch_bounds__(256) void transpose_half_kernel(
    const float* __restrict__ in, __half* __restrict__ out, int K, int N)
{
    __shared__ float t[32][33];
    int n0 = blockIdx.x * 32, k0 = blockIdx.y * 32;
    int tx = threadIdx.x & 31, ty = threadIdx.x >> 5;
    #pragma unroll
    for (int j = 0; j < 4; j++)
        t[ty + j*8][tx] = in[(size_t)(k0 + ty + j*8)*N + n0 + tx];
    __syncthreads();
    #pragma unroll
    for (int j = 0; j < 4; j++)
        out[(size_t)(n0 + ty + j*8)*K + k0 + tx] = __float2half_rn(t[tx][ty + j*8]);
}

// ---------------------------------------------------------------------------
// LayerNorm v2: warp-per-row (8 rows/block), shuffle-only reduction.
// ---------------------------------------------------------------------------
__global__ __launch_bounds__(256) void ln_kernel(
    const float* __restrict__ x, const float* __restrict__ gamma,
    const float* __restrict__ beta)
{
    const int warp = threadIdx.x >> 5, lane = threadIdx.x & 31;
    const int row = blockIdx.x * 8 + warp;
    const float4* xr = (const float4*)(x + (size_t)row*DIM);

    float4 v[8];
    float s = 0.f, ss = 0.f;
    #pragma unroll
    for (int j = 0; j < 8; j++) {
        v[j] = xr[lane + 32*j];
        s  += v[j].x + v[j].y + v[j].z + v[j].w;
        ss += v[j].x*v[j].x + v[j].y*v[j].y + v[j].z*v[j].z + v[j].w*v[j].w;
    }
    #pragma unroll
    for (int o = 16; o > 0; o >>= 1) {
        s  += __shfl_xor_sync(0xFFFFFFFFu, s,  o);
        ss += __shfl_xor_sync(0xFFFFFFFFu, ss, o);
    }
    float mu  = s  * (1.0f/DIM);
    float var = ss * (1.0f/DIM) - mu*mu;
    float inv = rsqrtf(var + 1e-5f);

    uint2* dst = (uint2*)(g_xn + (size_t)row*DIM);
    #pragma unroll
    for (int j = 0; j < 8; j++) {
        float4 g = ((const float4*)gamma)[lane + 32*j];
        float4 b = ((const float4*)beta)[lane + 32*j];
        __half2 h01 = __floats2half2_rn((v[j].x - mu)*inv*g.x + b.x,
                                        (v[j].y - mu)*inv*g.y + b.y);
        __half2 h23 = __floats2half2_rn((v[j].z - mu)*inv*g.z + b.z,
                                        (v[j].w - mu)*inv*g.w + b.w);
        uint2 pk;
        pk.x = *reinterpret_cast<unsigned*>(&h01);
        pk.y = *reinterpret_cast<unsigned*>(&h23);
        dst[lane + 32*j] = pk;
    }
}

// ---------------------------------------------------------------------------
// FP16 GEMM 128x128 (QKV): 4 warps, 64x64 warp tile, BK=64, 2-stage .cg.
// ---------------------------------------------------------------------------
#define GP 72                               // pitch in halves
#define GST (128*GP)                        // halves per operand stage
#define GEMM_SMEM (4*GST*sizeof(__half))    // 73728 B

__global__ __launch_bounds__(128) void gemm_f16(
    const __half* __restrict__ A, const __half* __restrict__ BT,
    __half* __restrict__ Ch, int M, int N, int K)
{
    extern __shared__ __half gsm[];
    __half* As = gsm;            // 2 stages [128][72]
    __half* Bs = gsm + 2*GST;    // 2 stages [128][72] (rows = n)

    const int tid  = threadIdx.x;
    const int lane = tid & 31;
    const int warp = tid >> 5;
    const int lr = lane >> 2, lc = lane & 3;
    const int g8 = lane >> 3;
    const int i8 = lane & 7;
    const int wm = (warp & 1) * 64;
    const int wn = (warp >> 1) * 64;
    const int bm = blockIdx.y * 128;
    const int bn = blockIdx.x * 128;

    int aoff[4];
    #pragma unroll
    for (int mt = 0; mt < 4; mt++)
        aoff[mt] = ((wm + mt*16 + (g8 & 1)*8 + i8)*GP + (g8 >> 1)*8) * 2;
    int boff[4];
    #pragma unroll
    for (int np = 0; np < 4; np++)
        boff[np] = ((wn + np*16 + ((g8 >> 1) & 1)*8 + i8)*GP + (g8 & 1)*8) * 2;

    float acc[4][8][4];
    #pragma unroll
    for (int i = 0; i < 4; i++)
        #pragma unroll
        for (int j = 0; j < 8; j++)
            #pragma unroll
            for (int q = 0; q < 4; q++) acc[i][j][q] = 0.f;

    const int NK = K / 64;

    #define G_LOAD(s, kt64)                                                      \
    {                                                                            \
        __half* as_ = As + (s)*GST;                                              \
        __half* bs_ = Bs + (s)*GST;                                              \
        _Pragma("unroll")                                                        \
        for (int hh = 0; hh < 8; hh++) {                                         \
            int c = tid + hh*128;                                                \
            int row = c >> 3, kc = (c & 7) * 8;                                  \
            unsigned da = (unsigned)__cvta_generic_to_shared(                    \
                                &as_[row*GP + kc]);                              \
            CPA(da, A + (size_t)(bm + row)*K + (kt64)*64 + kc);                  \
            unsigned db = (unsigned)__cvta_generic_to_shared(                    \
                                &bs_[row*GP + kc]);                              \
            CPA(db, BT + (size_t)(bn + row)*K + (kt64)*64 + kc);                 \
        }                                                                        \
        asm volatile("cp.async.commit_group;");                                  \
    }

    G_LOAD(0, 0)

    for (int kt = 0; kt < NK; kt++) {
        asm volatile("cp.async.wait_group 0;");
        __syncthreads();
        if (kt + 1 < NK) G_LOAD((kt+1)&1, kt+1)

        unsigned aBase = (unsigned)__cvta_generic_to_shared(As + (kt&1)*GST);
        unsigned bBase = (unsigned)__cvta_generic_to_shared(Bs + (kt&1)*GST);

        #pragma unroll
        for (int kk = 0; kk < 4; kk++) {
            const int kb = kk * 32;
            unsigned af[4][4];
            #pragma unroll
            for (int mt = 0; mt < 4; mt++)
                LDMX4(af[mt][0], af[mt][1], af[mt][2], af[mt][3],
                      aBase + aoff[mt] + kb);
            unsigned bf[8][2];
            #pragma unroll
            for (int np = 0; np < 4; np++)
                LDMX4(bf[2*np][0], bf[2*np][1], bf[2*np+1][0], bf[2*np+1][1],
                      bBase + boff[np] + kb);
            #pragma unroll
            for (int mt = 0; mt < 4; mt++)
                #pragma unroll
                for (int nt = 0; nt < 8; nt++)
                    MMA_F16(acc[mt][nt][0], acc[mt][nt][1],
                            acc[mt][nt][2], acc[mt][nt][3],
                            af[mt][0], af[mt][1], af[mt][2], af[mt][3],
                            bf[nt][0], bf[nt][1]);
        }
    }

    #pragma unroll
    for (int mt = 0; mt < 4; mt++) {
        int r0 = bm + wm + mt*16 + lr;
        #pragma unroll
        for (int nt = 0; nt < 8; nt++) {
            int cc = bn + wn + nt*8 + lc*2;
            __half2 v0 = __floats2half2_rn(acc[mt][nt][0], acc[mt][nt][1]);
            __half2 v1 = __floats2half2_rn(acc[mt][nt][2], acc[mt][nt][3]);
            *(__half2*)&Ch[(size_t)r0*N + cc]     = v0;
            *(__half2*)&Ch[(size_t)(r0+8)*N + cc] = v1;
        }
    }
}

// ---------------------------------------------------------------------------
// FP16 GEMM 64x128 (out-proj): fp32 output, 4 CTAs/SM (R14 measured-good).
// ---------------------------------------------------------------------------
#define GSTA (64*GP)
#define GSTB (128*GP)
#define GEMM64_SMEM (2*(GSTA+GSTB)*sizeof(__half))   // 55296 B

__global__ __launch_bounds__(128, 4) void gemm_f16_m64(
    const __half* __restrict__ A, const __half* __restrict__ BT,
    float* __restrict__ Cf, int M, int N, int K)
{
    extern __shared__ __half gsm[];
    __half* As = gsm;             // 2 stages [64][72]
    __half* Bs = gsm + 2*GSTA;    // 2 stages [128][72]

    const int tid  = threadIdx.x;
    const int lane = tid & 31;
    const int warp = tid >> 5;
    const int lr = lane >> 2, lc = lane & 3;
    const int g8 = lane >> 3;
    const int i8 = lane & 7;
    const int wm = (warp & 1) * 32;
    const int wn = (warp >> 1) * 64;
    const int bm = blockIdx.y * 64;
    const int bn = blockIdx.x * 128;

    int aoff[2];
    #pragma unroll
    for (int mt = 0; mt < 2; mt++)
        aoff[mt] = ((wm + mt*16 + (g8 & 1)*8 + i8)*GP + (g8 >> 1)*8) * 2;
    int boff[4];
    #pragma unroll
    for (int np = 0; np < 4; np++)
        boff[np] = ((wn + np*16 + ((g8 >> 1) & 1)*8 + i8)*GP + (g8 & 1)*8) * 2;

    float acc[2][8][4];
    #pragma unroll
    for (int i = 0; i < 2; i++)
        #pragma unroll
        for (int j = 0; j < 8; j++)
            #pragma unroll
            for (int q = 0; q < 4; q++) acc[i][j][q] = 0.f;

    const int NK = K / 64;

    #define G_LOAD64(s, kt64)                                                    \
    {                                                                            \
        __half* as_ = As + (s)*GSTA;                                             \
        __half* bs_ = Bs + (s)*GSTB;                                             \
        _Pragma("unroll")                                                        \
        for (int hh = 0; hh < 4; hh++) {                                         \
            int c = tid + hh*128;                                                \
            int row = c >> 3, kc = (c & 7) * 8;                                  \
            unsigned da = (unsigned)__cvta_generic_to_shared(                    \
                                &as_[row*GP + kc]);                              \
            CPA(da, A + (size_t)(bm + row)*K + (kt64)*64 + kc);                  \
        }                                                                        \
        _Pragma("unroll")                                                        \
        for (int hh = 0; hh < 8; hh++) {                                         \
            int c = tid + hh*128;                                                \
            int row = c >> 3, kc = (c & 7) * 8;                                  \
            unsigned db = (unsigned)__cvta_generic_to_shared(                    \
                                &bs_[row*GP + kc]);                              \
            CPA(db, BT + (size_t)(bn + row)*K + (kt64)*64 + kc);                 \
        }                                                                        \
        asm volatile("cp.async.commit_group;");                                  \
    }

    G_LOAD64(0, 0)

    for (int kt = 0; kt < NK; kt++) {
        asm volatile("cp.async.wait_group 0;");
        __syncthreads();
        if (kt + 1 < NK) G_LOAD64((kt+1)&1, kt+1)

        unsigned aBase = (unsigned)__cvta_generic_to_shared(As + (kt&1)*GSTA);
        unsigned bBase = (unsigned)__cvta_generic_to_shared(Bs + (kt&1)*GSTB);

        #pragma unroll
        for (int kk = 0; kk < 4; kk++) {
            const int kb = kk * 32;
            unsigned af[2][4];
            #pragma unroll
            for (int mt = 0; mt < 2; mt++)
                LDMX4(af[mt][0], af[mt][1], af[mt][2], af[mt][3],
                      aBase + aoff[mt] + kb);
            unsigned bf[8][2];
            #pragma unroll
            for (int np = 0; np < 4; np++)
                LDMX4(bf[2*np][0], bf[2*np][1], bf[2*np+1][0], bf[2*np+1][1],
                      bBase + boff[np] + kb);
            #pragma unroll
            for (int mt = 0; mt < 2; mt++)
                #pragma unroll
                for (int nt = 0; nt < 8; nt++)
                    MMA_F16(acc[mt][nt][0], acc[mt][nt][1],
                            acc[mt][nt][2], acc[mt][nt][3],
                            af[mt][0], af[mt][1], af[mt][2], af[mt][3],
                            bf[nt][0], bf[nt][1]);
        }
    }

    #pragma unroll
    for (int mt = 0; mt < 2; mt++) {
        int r0 = bm + wm + mt*16 + lr;
        #pragma unroll
        for (int nt = 0; nt < 8; nt++) {
            int cc = bn + wn + nt*8 + lc*2;
            *(float2*)&Cf[(size_t)r0*N + cc] =
                make_float2(acc[mt][nt][0], acc[mt][nt][1]);
            *(float2*)&Cf[(size_t)(r0+8)*N + cc] =
                make_float2(acc[mt][nt][2], acc[mt][nt][3]);
        }
    }
}

// ---------------------------------------------------------------------------
// FP16 flash attention (R14 128-row structure) with __launch_bounds__(128,3):
// caps regs at 170 to fit 3 CTAs/SM (12 warps, +50% latency hiding).
// ex2.f16x2 softmax, cp.async.cg, bias LDGs hoisted pre-wait.
// ---------------------------------------------------------------------------
#define AP 72
#define A_QP (128*AP)
#define A_KS (64*AP)
#define A_VS (64*AP)
#define ATTN_SMEM ((A_QP + 2*A_KS + 2*A_VS)*sizeof(__half)) // 55296 B

__global__ __launch_bounds__(128, 3) void attn_f16_kernel(const float* __restrict__ bias)
{
    extern __shared__ __half smh[];
    __half* QP  = smh;                      // [128][72]  Q then P
    __half* Ksm = smh + A_QP;               // [2][64][72]
    __half* Vsm = smh + A_QP + 2*A_KS;      // [2][64][72]

    const int b  = blockIdx.x;
    const int qt = blockIdx.y;
    const int h  = blockIdx.z;
    const int tid  = threadIdx.x;
    const int lane = tid & 31;
    const int warp = tid >> 5;
    const int wq = warp * 32;
    const int lr = lane >> 2, lc = lane & 3;
    const int g8 = lane >> 3;
    const int i8 = lane & 7;

    const __half* qbase = g_qkv + (size_t)(b*NSEQ + qt*128)*QKVW + h*DHEAD;
    const __half* kbase = g_qkv + (size_t)(b*NSEQ)*QKVW + INNER   + h*DHEAD;
    const __half* vbase = g_qkv + (size_t)(b*NSEQ)*QKVW + 2*INNER + h*DHEAD;
    const float*  bb0   = bias + ((size_t)h*NSEQ + qt*128 + wq)*NSEQ;

    int poff[2];
    #pragma unroll
    for (int mt = 0; mt < 2; mt++)
        poff[mt] = ((wq + mt*16 + (g8 & 1)*8 + i8)*AP + (g8 >> 1)*8) * 2;
    int koff[4];
    #pragma unroll
    for (int np = 0; np < 4; np++)
        koff[np] = ((np*16 + ((g8 >> 1) & 1)*8 + i8)*AP + (g8 & 1)*8) * 2;
    int voff[4];
    #pragma unroll
    for (int np = 0; np < 4; np++)
        voff[np] = (((g8 & 1)*8 + i8)*AP + np*16 + (g8 >> 1)*8) * 2;

    unsigned qpBase = (unsigned)__cvta_generic_to_shared(QP);

    // stage Q via cp.async (128 rows x 64 halves)
    #pragma unroll
    for (int p = 0; p < 8; p++) {
        int c = p*128 + tid;
        int row = c >> 3, col = (c & 7) * 8;
        unsigned dst = (unsigned)__cvta_generic_to_shared(&QP[row*AP + col]);
        CPA(dst, qbase + (size_t)row*QKVW + col);
    }

    #define KV_LOAD(s, ktl)                                                      \
    {                                                                            \
        __half* kd = Ksm + (s)*A_KS;                                             \
        __half* vd = Vsm + (s)*A_VS;                                             \
        _Pragma("unroll")                                                        \
        for (int p = 0; p < 4; p++) {                                            \
            int c = p*128 + tid;                                                 \
            int row = c >> 3, col = (c & 7) * 8;                                 \
            unsigned dk = (unsigned)__cvta_generic_to_shared(&kd[row*AP + col]); \
            CPA(dk, kbase + (size_t)((ktl)*64 + row)*QKVW + col);                \
            unsigned dv = (unsigned)__cvta_generic_to_shared(&vd[row*AP + col]); \
            CPA(dv, vbase + (size_t)((ktl)*64 + row)*QKVW + col);                \
        }                                                                        \
    }

    KV_LOAD(0, 0)
    asm volatile("cp.async.commit_group;");
    asm volatile("cp.async.wait_group 0;");
    __syncthreads();

    // extract Q fragments to registers, scaled by 0.125 (exact in fp16)
    const __half2 qsc = __float2half2_rn(0.125f);
    unsigned qf[4][2][4];
    #pragma unroll
    for (int k = 0; k < 4; k++) {
        int k16 = k*16;
        #pragma unroll
        for (int mt = 0; mt < 2; mt++) {
            int r0 = wq + mt*16 + lr;
            __half2 t0 = __hmul2(*(__half2*)&QP[(r0    )*AP + k16     + 2*lc], qsc);
            __half2 t1 = __hmul2(*(__half2*)&QP[(r0 + 8)*AP + k16     + 2*lc], qsc);
            __half2 t2 = __hmul2(*(__half2*)&QP[(r0    )*AP + k16 + 8 + 2*lc], qsc);
            __half2 t3 = __hmul2(*(__half2*)&QP[(r0 + 8)*AP + k16 + 8 + 2*lc], qsc);
            qf[k][mt][0] = *reinterpret_cast<unsigned*>(&t0);
            qf[k][mt][1] = *reinterpret_cast<unsigned*>(&t1);
            qf[k][mt][2] = *reinterpret_cast<unsigned*>(&t2);
            qf[k][mt][3] = *reinterpret_cast<unsigned*>(&t3);
        }
    }
    __syncthreads();

    float m[4], l[4];
    float co[2][8][4];
    #pragma unroll
    for (int i = 0; i < 4; i++) { m[i] = -1e30f; l[i] = 0.f; }
    #pragma unroll
    for (int mt = 0; mt < 2; mt++)
        #pragma unroll
        for (int nt = 0; nt < 8; nt++)
            #pragma unroll
            for (int q = 0; q < 4; q++) co[mt][nt][q] = 0.f;

    for (int kt = 0; kt < 16; kt++) {
        // bias-init LDGs before the K/V wait (latency hidden)
        float cs[2][8][4];
        const float* bb = bb0 + kt*64;
        #pragma unroll
        for (int mt = 0; mt < 2; mt++)
            #pragma unroll
            for (int hh = 0; hh < 2; hh++) {
                int roff = mt*16 + lr + 8*hh;
                #pragma unroll
                for (int nt = 0; nt < 8; nt++) {
                    float2 t = *(const float2*)(bb + (size_t)roff*NSEQ + nt*8 + 2*lc);
                    cs[mt][nt][2*hh]   = t.x;
                    cs[mt][nt][2*hh+1] = t.y;
                }
            }

        asm volatile("cp.async.wait_group 0;");
        __syncthreads();
        if (kt < 15) {
            KV_LOAD((kt+1)&1, kt+1)
            asm volatile("cp.async.commit_group;");
        }
        unsigned kBase = (unsigned)__cvta_generic_to_shared(Ksm + (kt&1)*A_KS);
        unsigned vBase = (unsigned)__cvta_generic_to_shared(Vsm + (kt&1)*A_VS);

        // S = Q K^T + bias (A regs, B=K via ldmatrix)
        #pragma unroll
        for (int k = 0; k < 4; k++) {
            int kb = k*32;
            unsigned bf[8][2];
            #pragma unroll
            for (int np = 0; np < 4; np++)
                LDMX4(bf[2*np][0], bf[2*np][1], bf[2*np+1][0], bf[2*np+1][1],
                      kBase + koff[np] + kb);
            #pragma unroll
            for (int mt = 0; mt < 2; mt++)
                #pragma unroll
                for (int nt = 0; nt < 8; nt++)
                    MMA_F16(cs[mt][nt][0], cs[mt][nt][1],
                            cs[mt][nt][2], cs[mt][nt][3],
                            qf[k][mt][0], qf[k][mt][1],
                            qf[k][mt][2], qf[k][mt][3],
                            bf[nt][0], bf[nt][1]);
        }

        // online softmax; exp via ex2.approx.f16x2 -> P smem directly
        #pragma unroll
        for (int mt = 0; mt < 2; mt++)
            #pragma unroll
            for (int hh = 0; hh < 2; hh++) {
                int idx = mt*2 + hh;
                float mx = -1e30f;
                #pragma unroll
                for (int nt = 0; nt < 8; nt++)
                    mx = fmaxf(mx, fmaxf(cs[mt][nt][2*hh], cs[mt][nt][2*hh+1]));
                mx = fmaxf(mx, __shfl_xor_sync(0xFFFFFFFFu, mx, 1));
                mx = fmaxf(mx, __shfl_xor_sync(0xFFFFFFFFu, mx, 2));
                float mnew = fmaxf(m[idx], mx);
                float corr = __expf(m[idx] - mnew);
                m[idx] = mnew;
                float ls = 0.f;
                int prow = (wq + mt*16 + lr + 8*hh)*AP + 2*lc;
                float nm2 = mnew * LOG2E;
                #pragma unroll
                for (int nt = 0; nt < 8; nt++) {
                    unsigned ph = ex2_f16x2(
                        __fmaf_rn(cs[mt][nt][2*hh],   LOG2E, -nm2),
                        __fmaf_rn(cs[mt][nt][2*hh+1], LOG2E, -nm2));
                    *(unsigned*)&QP[prow + nt*8] = ph;
                    __half2 phh = *reinterpret_cast<__half2*>(&ph);
                    float2 pf2 = __half22float2(phh);
                    ls += pf2.x + pf2.y;
                }
                ls += __shfl_xor_sync(0xFFFFFFFFu, ls, 1);
                ls += __shfl_xor_sync(0xFFFFFFFFu, ls, 2);
                l[idx] = l[idx]*corr + ls;
                #pragma unroll
                for (int nt = 0; nt < 8; nt++) {
                    co[mt][nt][2*hh]   *= corr;
                    co[mt][nt][2*hh+1] *= corr;
                }
            }
        __syncwarp();

        // O += P V  (P via ldmatrix, V via ldmatrix.trans)
        #pragma unroll
        for (int k = 0; k < 4; k++) {
            int kvrow = k*16*AP*2;
            unsigned af[2][4];
            #pragma unroll
            for (int mt = 0; mt < 2; mt++)
                LDMX4(af[mt][0], af[mt][1], af[mt][2], af[mt][3],
                      qpBase + poff[mt] + k*32);
            unsigned bf[8][2];
            #pragma unroll
            for (int np = 0; np < 4; np++)
                LDMX4T(bf[2*np][0], bf[2*np][1], bf[2*np+1][0], bf[2*np+1][1],
                       vBase + voff[np] + kvrow);
            #pragma unroll
            for (int mt = 0; mt < 2; mt++)
                #pragma unroll
                for (int nt = 0; nt < 8; nt++)
                    MMA_F16(co[mt][nt][0], co[mt][nt][1],
                            co[mt][nt][2], co[mt][nt][3],
                            af[mt][0], af[mt][1], af[mt][2], af[mt][3],
                            bf[nt][0], bf[nt][1]);
        }
    }

    // epilogue: normalize, write fp16 [b,n,(h d)]
    #pragma unroll
    for (int mt = 0; mt < 2; mt++)
        #pragma unroll
        for (int hh = 0; hh < 2; hh++) {
            int idx = mt*2 + hh;
            float inv = 1.0f / l[idx];
            size_t grow = (size_t)(b*NSEQ + qt*128 + wq + mt*16 + lr + 8*hh);
            #pragma unroll
            for (int nt = 0; nt < 8; nt++) {
                __half2 o = __floats2half2_rn(co[mt][nt][2*hh]   * inv,
                                              co[mt][nt][2*hh+1] * inv);
                *(__half2*)&g_att[grow*INNER + h*DHEAD + nt*8 + 2*lc] = o;
            }
        }
}

// ---------------------------------------------------------------------------
extern "C" void kernel_launch(void* const* d_in, const int* in_sizes, int n_in,
                              void* d_out, int out_size)
{
    const float* x     = (const float*)d_in[0];
    const float* gamma = (const float*)d_in[1];
    const float* beta  = (const float*)d_in[2];
    const float* wqkv  = (const float*)d_in[3];
    const float* wout  = (const float*)d_in[4];
    const float* bias  = (const float*)d_in[5];
    float* out = (float*)d_out;

    __half *xn, *qkv, *att, *wqkvT, *woutT;
    cudaGetSymbolAddress((void**)&xn,    g_xn);
    cudaGetSymbolAddress((void**)&qkv,   g_qkv);
    cudaGetSymbolAddress((void**)&att,   g_att);
    cudaGetSymbolAddress((void**)&wqkvT, g_wqkvT);
    cudaGetSymbolAddress((void**)&woutT, g_woutT);

    cudaFuncSetAttribute(gemm_f16,
                         cudaFuncAttributeMaxDynamicSharedMemorySize,
                         (int)GEMM_SMEM);
    cudaFuncSetAttribute(gemm_f16_m64,
                         cudaFuncAttributeMaxDynamicSharedMemorySize,
                         (int)GEMM64_SMEM);
    cudaFuncSetAttribute(attn_f16_kernel,
                         cudaFuncAttributeMaxDynamicSharedMemorySize,
                         (int)ATTN_SMEM);

    transpose_half_kernel<<<dim3(QKVW/32, DIM/32), 256>>>(wqkv, wqkvT, DIM, QKVW);
    transpose_half_kernel<<<dim3(DIM/32, INNER/32), 256>>>(wout, woutT, INNER, DIM);
    ln_kernel<<<ROWS/8, 256>>>(x, gamma, beta);
    gemm_f16<<<dim3(QKVW/128, ROWS/128), 128, GEMM_SMEM>>>(
        xn, wqkvT, qkv, ROWS, QKVW, DIM);
    attn_f16_kernel<<<dim3(BATCH, NSEQ/128, HEADS), 128, ATTN_SMEM>>>(bias);
    gemm_f16_m64<<<dim3(DIM/128, ROWS/64), 128, GEMM64_SMEM>>>(
        att, woutT, out, ROWS, DIM, INNER);
}

// round 17
// speedup vs baseline: 1.0885x; 1.0885x over previous
#include <cuda_runtime.h>
#include <cuda_fp16.h>
#include <stdint.h>
#include <math.h>

#define BATCH   8
#define NSEQ    1024
#define DIM     1024
#define HEADS   16
#define DHEAD   64
#define INNER   1024
#define ROWS    (BATCH*NSEQ)   // 8192
#define QKVW    (3*INNER)      // 3072

// Scratch (device globals: allocation-free per harness rules)
__device__ __half g_xn   [ROWS*DIM];     // fp16 LN output
__device__ __half g_qkv  [ROWS*QKVW];    // fp16 QKV
__device__ __half g_att  [ROWS*INNER];   // fp16 attention output
__device__ __half g_wqkvT[QKVW*DIM];     // W_qkv^T fp16 [n][k]
__device__ __half g_woutT[DIM*INNER];    // W_out^T fp16 [n][k]

#define LDMX4(r0,r1,r2,r3,addr)                                              \
    asm volatile("ldmatrix.sync.aligned.m8n8.x4.shared.b16 "                 \
                 "{%0,%1,%2,%3}, [%4];"                                      \
                 : "=r"(r0), "=r"(r1), "=r"(r2), "=r"(r3) : "r"(addr))

#define LDMX4T(r0,r1,r2,r3,addr)                                             \
    asm volatile("ldmatrix.sync.aligned.m8n8.x4.trans.shared.b16 "           \
                 "{%0,%1,%2,%3}, [%4];"                                      \
                 : "=r"(r0), "=r"(r1), "=r"(r2), "=r"(r3) : "r"(addr))

#define MMA_F16(c0,c1,c2,c3,a0,a1,a2,a3,b0,b1)                               \
    asm volatile(                                                            \
        "mma.sync.aligned.m16n8k16.row.col.f32.f16.f16.f32 "                 \
        "{%0,%1,%2,%3},{%4,%5,%6,%7},{%8,%9},{%0,%1,%2,%3};"                 \
        : "+f"(c0), "+f"(c1), "+f"(c2), "+f"(c3)                             \
        : "r"(a0), "r"(a1), "r"(a2), "r"(a3), "r"(b0), "r"(b1))

#define CPA(dst, src)                                                        \
    asm volatile("cp.async.cg.shared.global [%0], [%1], 16;"                 \
                 :: "r"(dst), "l"(src))

// ex2 on packed fp16x2: one MUFU op for two values.
__device__ __forceinline__ unsigned ex2_f16x2(float a, float b) {
    __half2 h = __floats2half2_rn(a, b);
    unsigned hi = *reinterpret_cast<unsigned*>(&h);
    unsigned r;
    asm volatile("ex2.approx.f16x2 %0, %1;" : "=r"(r) : "r"(hi));
    return r;
}

#define LOG2E 1.44269504088896f

// ---------------------------------------------------------------------------
// Weight transpose + fp16 convert: out[n*K + k] = half(in[k*N + n]).
// ---------------------------------------------------------------------------
__global__ __launch_bounds__(256) void transpose_half_kernel(
    const float* __restrict__ in, __half* __restrict__ out, int K, int N)
{
    __shared__ float t[32][33];
    int n0 = blockIdx.x * 32, k0 = blockIdx.y * 32;
    int tx = threadIdx.x & 31, ty = threadIdx.x >> 5;
    #pragma unroll
    for (int j = 0; j < 4; j++)
        t[ty + j*8][tx] = in[(size_t)(k0 + ty + j*8)*N + n0 + tx];
    __syncthreads();
    #pragma unroll
    for (int j = 0; j < 4; j++)
        out[(size_t)(n0 + ty + j*8)*K + k0 + tx] = __float2half_rn(t[tx][ty + j*8]);
}

// ---------------------------------------------------------------------------
// LayerNorm: warp-per-row (8 rows/block), shuffle-only reduction.
// ---------------------------------------------------------------------------
__global__ __launch_bounds__(256) void ln_kernel(
    const float* __restrict__ x, const float* __restrict__ gamma,
    const float* __restrict__ beta)
{
    const int warp = threadIdx.x >> 5, lane = threadIdx.x & 31;
    const int row = blockIdx.x * 8 + warp;
    const float4* xr = (const float4*)(x + (size_t)row*DIM);

    float4 v[8];
    float s = 0.f, ss = 0.f;
    #pragma unroll
    for (int j = 0; j < 8; j++) {
        v[j] = xr[lane + 32*j];
        s  += v[j].x + v[j].y + v[j].z + v[j].w;
        ss += v[j].x*v[j].x + v[j].y*v[j].y + v[j].z*v[j].z + v[j].w*v[j].w;
    }
    #pragma unroll
    for (int o = 16; o > 0; o >>= 1) {
        s  += __shfl_xor_sync(0xFFFFFFFFu, s,  o);
        ss += __shfl_xor_sync(0xFFFFFFFFu, ss, o);
    }
    float mu  = s  * (1.0f/DIM);
    float var = ss * (1.0f/DIM) - mu*mu;
    float inv = rsqrtf(var + 1e-5f);

    uint2* dst = (uint2*)(g_xn + (size_t)row*DIM);
    #pragma unroll
    for (int j = 0; j < 8; j++) {
        float4 g = ((const float4*)gamma)[lane + 32*j];
        float4 b = ((const float4*)beta)[lane + 32*j];
        __half2 h01 = __floats2half2_rn((v[j].x - mu)*inv*g.x + b.x,
                                        (v[j].y - mu)*inv*g.y + b.y);
        __half2 h23 = __floats2half2_rn((v[j].z - mu)*inv*g.z + b.z,
                                        (v[j].w - mu)*inv*g.w + b.w);
        uint2 pk;
        pk.x = *reinterpret_cast<unsigned*>(&h01);
        pk.y = *reinterpret_cast<unsigned*>(&h23);
        dst[lane + 32*j] = pk;
    }
}

// ---------------------------------------------------------------------------
// FP16 GEMM 128x128 (QKV): 4 warps, 64x64 warp tile, BK=64, 2-stage .cg.
// ---------------------------------------------------------------------------
#define GP 72                               // pitch in halves
#define GST (128*GP)                        // halves per operand stage
#define GEMM_SMEM (4*GST*sizeof(__half))    // 73728 B

__global__ __launch_bounds__(128) void gemm_f16(
    const __half* __restrict__ A, const __half* __restrict__ BT,
    __half* __restrict__ Ch, int M, int N, int K)
{
    extern __shared__ __half gsm[];
    __half* As = gsm;            // 2 stages [128][72]
    __half* Bs = gsm + 2*GST;    // 2 stages [128][72] (rows = n)

    const int tid  = threadIdx.x;
    const int lane = tid & 31;
    const int warp = tid >> 5;
    const int lr = lane >> 2, lc = lane & 3;
    const int g8 = lane >> 3;
    const int i8 = lane & 7;
    const int wm = (warp & 1) * 64;
    const int wn = (warp >> 1) * 64;
    const int bm = blockIdx.y * 128;
    const int bn = blockIdx.x * 128;

    int aoff[4];
    #pragma unroll
    for (int mt = 0; mt < 4; mt++)
        aoff[mt] = ((wm + mt*16 + (g8 & 1)*8 + i8)*GP + (g8 >> 1)*8) * 2;
    int boff[4];
    #pragma unroll
    for (int np = 0; np < 4; np++)
        boff[np] = ((wn + np*16 + ((g8 >> 1) & 1)*8 + i8)*GP + (g8 & 1)*8) * 2;

    float acc[4][8][4];
    #pragma unroll
    for (int i = 0; i < 4; i++)
        #pragma unroll
        for (int j = 0; j < 8; j++)
            #pragma unroll
            for (int q = 0; q < 4; q++) acc[i][j][q] = 0.f;

    const int NK = K / 64;

    #define G_LOAD(s, kt64)                                                      \
    {                                                                            \
        __half* as_ = As + (s)*GST;                                              \
        __half* bs_ = Bs + (s)*GST;                                              \
        _Pragma("unroll")                                                        \
        for (int hh = 0; hh < 8; hh++) {                                         \
            int c = tid + hh*128;                                                \
            int row = c >> 3, kc = (c & 7) * 8;                                  \
            unsigned da = (unsigned)__cvta_generic_to_shared(                    \
                                &as_[row*GP + kc]);                              \
            CPA(da, A + (size_t)(bm + row)*K + (kt64)*64 + kc);                  \
            unsigned db = (unsigned)__cvta_generic_to_shared(                    \
                                &bs_[row*GP + kc]);                              \
            CPA(db, BT + (size_t)(bn + row)*K + (kt64)*64 + kc);                 \
        }                                                                        \
        asm volatile("cp.async.commit_group;");                                  \
    }

    G_LOAD(0, 0)

    for (int kt = 0; kt < NK; kt++) {
        asm volatile("cp.async.wait_group 0;");
        __syncthreads();
        if (kt + 1 < NK) G_LOAD((kt+1)&1, kt+1)

        unsigned aBase = (unsigned)__cvta_generic_to_shared(As + (kt&1)*GST);
        unsigned bBase = (unsigned)__cvta_generic_to_shared(Bs + (kt&1)*GST);

        #pragma unroll
        for (int kk = 0; kk < 4; kk++) {
            const int kb = kk * 32;
            unsigned af[4][4];
            #pragma unroll
            for (int mt = 0; mt < 4; mt++)
                LDMX4(af[mt][0], af[mt][1], af[mt][2], af[mt][3],
                      aBase + aoff[mt] + kb);
            unsigned bf[8][2];
            #pragma unroll
            for (int np = 0; np < 4; np++)
                LDMX4(bf[2*np][0], bf[2*np][1], bf[2*np+1][0], bf[2*np+1][1],
                      bBase + boff[np] + kb);
            #pragma unroll
            for (int mt = 0; mt < 4; mt++)
                #pragma unroll
                for (int nt = 0; nt < 8; nt++)
                    MMA_F16(acc[mt][nt][0], acc[mt][nt][1],
                            acc[mt][nt][2], acc[mt][nt][3],
                            af[mt][0], af[mt][1], af[mt][2], af[mt][3],
                            bf[nt][0], bf[nt][1]);
        }
    }

    #pragma unroll
    for (int mt = 0; mt < 4; mt++) {
        int r0 = bm + wm + mt*16 + lr;
        #pragma unroll
        for (int nt = 0; nt < 8; nt++) {
            int cc = bn + wn + nt*8 + lc*2;
            __half2 v0 = __floats2half2_rn(acc[mt][nt][0], acc[mt][nt][1]);
            __half2 v1 = __floats2half2_rn(acc[mt][nt][2], acc[mt][nt][3]);
            *(__half2*)&Ch[(size_t)r0*N + cc]     = v0;
            *(__half2*)&Ch[(size_t)(r0+8)*N + cc] = v1;
        }
    }
}

// ---------------------------------------------------------------------------
// FP16 GEMM 64x128 (out-proj): fp32 output, 4 CTAs/SM.
// ---------------------------------------------------------------------------
#define GSTA (64*GP)
#define GSTB (128*GP)
#define GEMM64_SMEM (2*(GSTA+GSTB)*sizeof(__half))   // 55296 B

__global__ __launch_bounds__(128, 4) void gemm_f16_m64(
    const __half* __restrict__ A, const __half* __restrict__ BT,
    float* __restrict__ Cf, int M, int N, int K)
{
    extern __shared__ __half gsm[];
    __half* As = gsm;             // 2 stages [64][72]
    __half* Bs = gsm + 2*GSTA;    // 2 stages [128][72]

    const int tid  = threadIdx.x;
    const int lane = tid & 31;
    const int warp = tid >> 5;
    const int lr = lane >> 2, lc = lane & 3;
    const int g8 = lane >> 3;
    const int i8 = lane & 7;
    const int wm = (warp & 1) * 32;
    const int wn = (warp >> 1) * 64;
    const int bm = blockIdx.y * 64;
    const int bn = blockIdx.x * 128;

    int aoff[2];
    #pragma unroll
    for (int mt = 0; mt < 2; mt++)
        aoff[mt] = ((wm + mt*16 + (g8 & 1)*8 + i8)*GP + (g8 >> 1)*8) * 2;
    int boff[4];
    #pragma unroll
    for (int np = 0; np < 4; np++)
        boff[np] = ((wn + np*16 + ((g8 >> 1) & 1)*8 + i8)*GP + (g8 & 1)*8) * 2;

    float acc[2][8][4];
    #pragma unroll
    for (int i = 0; i < 2; i++)
        #pragma unroll
        for (int j = 0; j < 8; j++)
            #pragma unroll
            for (int q = 0; q < 4; q++) acc[i][j][q] = 0.f;

    const int NK = K / 64;

    #define G_LOAD64(s, kt64)                                                    \
    {                                                                            \
        __half* as_ = As + (s)*GSTA;                                             \
        __half* bs_ = Bs + (s)*GSTB;                                             \
        _Pragma("unroll")                                                        \
        for (int hh = 0; hh < 4; hh++) {                                         \
            int c = tid + hh*128;                                                \
            int row = c >> 3, kc = (c & 7) * 8;                                  \
            unsigned da = (unsigned)__cvta_generic_to_shared(                    \
                                &as_[row*GP + kc]);                              \
            CPA(da, A + (size_t)(bm + row)*K + (kt64)*64 + kc);                  \
        }                                                                        \
        _Pragma("unroll")                                                        \
        for (int hh = 0; hh < 8; hh++) {                                         \
            int c = tid + hh*128;                                                \
            int row = c >> 3, kc = (c & 7) * 8;                                  \
            unsigned db = (unsigned)__cvta_generic_to_shared(                    \
                                &bs_[row*GP + kc]);                              \
            CPA(db, BT + (size_t)(bn + row)*K + (kt64)*64 + kc);                 \
        }                                                                        \
        asm volatile("cp.async.commit_group;");                                  \
    }

    G_LOAD64(0, 0)

    for (int kt = 0; kt < NK; kt++) {
        asm volatile("cp.async.wait_group 0;");
        __syncthreads();
        if (kt + 1 < NK) G_LOAD64((kt+1)&1, kt+1)

        unsigned aBase = (unsigned)__cvta_generic_to_shared(As + (kt&1)*GSTA);
        unsigned bBase = (unsigned)__cvta_generic_to_shared(Bs + (kt&1)*GSTB);

        #pragma unroll
        for (int kk = 0; kk < 4; kk++) {
            const int kb = kk * 32;
            unsigned af[2][4];
            #pragma unroll
            for (int mt = 0; mt < 2; mt++)
                LDMX4(af[mt][0], af[mt][1], af[mt][2], af[mt][3],
                      aBase + aoff[mt] + kb);
            unsigned bf[8][2];
            #pragma unroll
            for (int np = 0; np < 4; np++)
                LDMX4(bf[2*np][0], bf[2*np][1], bf[2*np+1][0], bf[2*np+1][1],
                      bBase + boff[np] + kb);
            #pragma unroll
            for (int mt = 0; mt < 2; mt++)
                #pragma unroll
                for (int nt = 0; nt < 8; nt++)
                    MMA_F16(acc[mt][nt][0], acc[mt][nt][1],
                            acc[mt][nt][2], acc[mt][nt][3],
                            af[mt][0], af[mt][1], af[mt][2], af[mt][3],
                            bf[nt][0], bf[nt][1]);
        }
    }

    #pragma unroll
    for (int mt = 0; mt < 2; mt++) {
        int r0 = bm + wm + mt*16 + lr;
        #pragma unroll
        for (int nt = 0; nt < 8; nt++) {
            int cc = bn + wn + nt*8 + lc*2;
            *(float2*)&Cf[(size_t)r0*N + cc] =
                make_float2(acc[mt][nt][0], acc[mt][nt][1]);
            *(float2*)&Cf[(size_t)(r0+8)*N + cc] =
                make_float2(acc[mt][nt][2], acc[mt][nt][3]);
        }
    }
}

// ---------------------------------------------------------------------------
// FP16 flash attention (R14 measured-best: 128 q-rows, natural registers,
// ex2.f16x2 softmax, cp.async.cg, bias LDGs hoisted pre-wait).
// ---------------------------------------------------------------------------
#define AP 72
#define A_QP (128*AP)
#define A_KS (64*AP)
#define A_VS (64*AP)
#define ATTN_SMEM ((A_QP + 2*A_KS + 2*A_VS)*sizeof(__half)) // 55296 B

__global__ __launch_bounds__(128) void attn_f16_kernel(const float* __restrict__ bias)
{
    extern __shared__ __half smh[];
    __half* QP  = smh;                      // [128][72]  Q then P
    __half* Ksm = smh + A_QP;               // [2][64][72]
    __half* Vsm = smh + A_QP + 2*A_KS;      // [2][64][72]

    const int b  = blockIdx.x;
    const int qt = blockIdx.y;
    const int h  = blockIdx.z;
    const int tid  = threadIdx.x;
    const int lane = tid & 31;
    const int warp = tid >> 5;
    const int wq = warp * 32;
    const int lr = lane >> 2, lc = lane & 3;
    const int g8 = lane >> 3;
    const int i8 = lane & 7;

    const __half* qbase = g_qkv + (size_t)(b*NSEQ + qt*128)*QKVW + h*DHEAD;
    const __half* kbase = g_qkv + (size_t)(b*NSEQ)*QKVW + INNER   + h*DHEAD;
    const __half* vbase = g_qkv + (size_t)(b*NSEQ)*QKVW + 2*INNER + h*DHEAD;
    const float*  bb0   = bias + ((size_t)h*NSEQ + qt*128 + wq)*NSEQ;

    int poff[2];
    #pragma unroll
    for (int mt = 0; mt < 2; mt++)
        poff[mt] = ((wq + mt*16 + (g8 & 1)*8 + i8)*AP + (g8 >> 1)*8) * 2;
    int koff[4];
    #pragma unroll
    for (int np = 0; np < 4; np++)
        koff[np] = ((np*16 + ((g8 >> 1) & 1)*8 + i8)*AP + (g8 & 1)*8) * 2;
    int voff[4];
    #pragma unroll
    for (int np = 0; np < 4; np++)
        voff[np] = (((g8 & 1)*8 + i8)*AP + np*16 + (g8 >> 1)*8) * 2;

    unsigned qpBase = (unsigned)__cvta_generic_to_shared(QP);

    // stage Q via cp.async (128 rows x 64 halves)
    #pragma unroll
    for (int p = 0; p < 8; p++) {
        int c = p*128 + tid;
        int row = c >> 3, col = (c & 7) * 8;
        unsigned dst = (unsigned)__cvta_generic_to_shared(&QP[row*AP + col]);
        CPA(dst, qbase + (size_t)row*QKVW + col);
    }

    #define KV_LOAD(s, ktl)                                                      \
    {                                                                            \
        __half* kd = Ksm + (s)*A_KS;                                             \
        __half* vd = Vsm + (s)*A_VS;                                             \
        _Pragma("unroll")                                                        \
        for (int p = 0; p < 4; p++) {                                            \
            int c = p*128 + tid;                                                 \
            int row = c >> 3, col = (c & 7) * 8;                                 \
            unsigned dk = (unsigned)__cvta_generic_to_shared(&kd[row*AP + col]); \
            CPA(dk, kbase + (size_t)((ktl)*64 + row)*QKVW + col);                \
            unsigned dv = (unsigned)__cvta_generic_to_shared(&vd[row*AP + col]); \
            CPA(dv, vbase + (size_t)((ktl)*64 + row)*QKVW + col);                \
        }                                                                        \
    }

    KV_LOAD(0, 0)
    asm volatile("cp.async.commit_group;");
    asm volatile("cp.async.wait_group 0;");
    __syncthreads();

    // extract Q fragments to registers, scaled by 0.125 (exact in fp16)
    const __half2 qsc = __float2half2_rn(0.125f);
    unsigned qf[4][2][4];
    #pragma unroll
    for (int k = 0; k < 4; k++) {
        int k16 = k*16;
        #pragma unroll
        for (int mt = 0; mt < 2; mt++) {
            int r0 = wq + mt*16 + lr;
            __half2 t0 = __hmul2(*(__half2*)&QP[(r0    )*AP + k16     + 2*lc], qsc);
            __half2 t1 = __hmul2(*(__half2*)&QP[(r0 + 8)*AP + k16     + 2*lc], qsc);
            __half2 t2 = __hmul2(*(__half2*)&QP[(r0    )*AP + k16 + 8 + 2*lc], qsc);
            __half2 t3 = __hmul2(*(__half2*)&QP[(r0 + 8)*AP + k16 + 8 + 2*lc], qsc);
            qf[k][mt][0] = *reinterpret_cast<unsigned*>(&t0);
            qf[k][mt][1] = *reinterpret_cast<unsigned*>(&t1);
            qf[k][mt][2] = *reinterpret_cast<unsigned*>(&t2);
            qf[k][mt][3] = *reinterpret_cast<unsigned*>(&t3);
        }
    }
    __syncthreads();

    float m[4], l[4];
    float co[2][8][4];
    #pragma unroll
    for (int i = 0; i < 4; i++) { m[i] = -1e30f; l[i] = 0.f; }
    #pragma unroll
    for (int mt = 0; mt < 2; mt++)
        #pragma unroll
        for (int nt = 0; nt < 8; nt++)
            #pragma unroll
            for (int q = 0; q < 4; q++) co[mt][nt][q] = 0.f;

    for (int kt = 0; kt < 16; kt++) {
        // bias-init LDGs before the K/V wait (latency hidden)
        float cs[2][8][4];
        const float* bb = bb0 + kt*64;
        #pragma unroll
        for (int mt = 0; mt < 2; mt++)
            #pragma unroll
            for (int hh = 0; hh < 2; hh++) {
                int roff = mt*16 + lr + 8*hh;
                #pragma unroll
                for (int nt = 0; nt < 8; nt++) {
                    float2 t = *(const float2*)(bb + (size_t)roff*NSEQ + nt*8 + 2*lc);
                    cs[mt][nt][2*hh]   = t.x;
                    cs[mt][nt][2*hh+1] = t.y;
                }
            }

        asm volatile("cp.async.wait_group 0;");
        __syncthreads();
        if (kt < 15) {
            KV_LOAD((kt+1)&1, kt+1)
            asm volatile("cp.async.commit_group;");
        }
        unsigned kBase = (unsigned)__cvta_generic_to_shared(Ksm + (kt&1)*A_KS);
        unsigned vBase = (unsigned)__cvta_generic_to_shared(Vsm + (kt&1)*A_VS);

        // S = Q K^T + bias (A regs, B=K via ldmatrix)
        #pragma unroll
        for (int k = 0; k < 4; k++) {
            int kb = k*32;
            unsigned bf[8][2];
            #pragma unroll
            for (int np = 0; np < 4; np++)
                LDMX4(bf[2*np][0], bf[2*np][1], bf[2*np+1][0], bf[2*np+1][1],
                      kBase + koff[np] + kb);
            #pragma unroll
            for (int mt = 0; mt < 2; mt++)
                #pragma unroll
                for (int nt = 0; nt < 8; nt++)
                    MMA_F16(cs[mt][nt][0], cs[mt][nt][1],
                            cs[mt][nt][2], cs[mt][nt][3],
                            qf[k][mt][0], qf[k][mt][1],
                            qf[k][mt][2], qf[k][mt][3],
                            bf[nt][0], bf[nt][1]);
        }

        // online softmax; exp via ex2.approx.f16x2 -> P smem directly
        #pragma unroll
        for (int mt = 0; mt < 2; mt++)
            #pragma unroll
            for (int hh = 0; hh < 2; hh++) {
                int idx = mt*2 + hh;
                float mx = -1e30f;
                #pragma unroll
                for (int nt = 0; nt < 8; nt++)
                    mx = fmaxf(mx, fmaxf(cs[mt][nt][2*hh], cs[mt][nt][2*hh+1]));
                mx = fmaxf(mx, __shfl_xor_sync(0xFFFFFFFFu, mx, 1));
                mx = fmaxf(mx, __shfl_xor_sync(0xFFFFFFFFu, mx, 2));
                float mnew = fmaxf(m[idx], mx);
                float corr = __expf(m[idx] - mnew);
                m[idx] = mnew;
                float ls = 0.f;
                int prow = (wq + mt*16 + lr + 8*hh)*AP + 2*lc;
                float nm2 = mnew * LOG2E;
                #pragma unroll
                for (int nt = 0; nt < 8; nt++) {
                    unsigned ph = ex2_f16x2(
                        __fmaf_rn(cs[mt][nt][2*hh],   LOG2E, -nm2),
                        __fmaf_rn(cs[mt][nt][2*hh+1], LOG2E, -nm2));
                    *(unsigned*)&QP[prow + nt*8] = ph;
                    __half2 phh = *reinterpret_cast<__half2*>(&ph);
                    float2 pf2 = __half22float2(phh);
                    ls += pf2.x + pf2.y;
                }
                ls += __shfl_xor_sync(0xFFFFFFFFu, ls, 1);
                ls += __shfl_xor_sync(0xFFFFFFFFu, ls, 2);
                l[idx] = l[idx]*corr + ls;
                #pragma unroll
                for (int nt = 0; nt < 8; nt++) {
                    co[mt][nt][2*hh]   *= corr;
                    co[mt][nt][2*hh+1] *= corr;
                }
            }
        __syncwarp();

        // O += P V  (P via ldmatrix, V via ldmatrix.trans)
        #pragma unroll
        for (int k = 0; k < 4; k++) {
            int kvrow = k*16*AP*2;
            unsigned af[2][4];
            #pragma unroll
            for (int mt = 0; mt < 2; mt++)
                LDMX4(af[mt][0], af[mt][1], af[mt][2], af[mt][3],
                      qpBase + poff[mt] + k*32);
            unsigned bf[8][2];
            #pragma unroll
            for (int np = 0; np < 4; np++)
                LDMX4T(bf[2*np][0], bf[2*np][1], bf[2*np+1][0], bf[2*np+1][1],
                       vBase + voff[np] + kvrow);
            #pragma unroll
            for (int mt = 0; mt < 2; mt++)
                #pragma unroll
                for (int nt = 0; nt < 8; nt++)
                    MMA_F16(co[mt][nt][0], co[mt][nt][1],
                            co[mt][nt][2], co[mt][nt][3],
                            af[mt][0], af[mt][1], af[mt][2], af[mt][3],
                            bf[nt][0], bf[nt][1]);
        }
    }

    // epilogue: normalize, write fp16 [b,n,(h d)]
    #pragma unroll
    for (int mt = 0; mt < 2; mt++)
        #pragma unroll
        for (int hh = 0; hh < 2; hh++) {
            int idx = mt*2 + hh;
            float inv = 1.0f / l[idx];
            size_t grow = (size_t)(b*NSEQ + qt*128 + wq + mt*16 + lr + 8*hh);
            #pragma unroll
            for (int nt = 0; nt < 8; nt++) {
                __half2 o = __floats2half2_rn(co[mt][nt][2*hh]   * inv,
                                              co[mt][nt][2*hh+1] * inv);
                *(__half2*)&g_att[grow*INNER + h*DHEAD + nt*8 + 2*lc] = o;
            }
        }
}

// ---------------------------------------------------------------------------
extern "C" void kernel_launch(void* const* d_in, const int* in_sizes, int n_in,
                              void* d_out, int out_size)
{
    const float* x     = (const float*)d_in[0];
    const float* gamma = (const float*)d_in[1];
    const float* beta  = (const float*)d_in[2];
    const float* wqkv  = (const float*)d_in[3];
    const float* wout  = (const float*)d_in[4];
    const float* bias  = (const float*)d_in[5];
    float* out = (float*)d_out;

    __half *xn, *qkv, *att, *wqkvT, *woutT;
    cudaGetSymbolAddress((void**)&xn,    g_xn);
    cudaGetSymbolAddress((void**)&qkv,   g_qkv);
    cudaGetSymbolAddress((void**)&att,   g_att);
    cudaGetSymbolAddress((void**)&wqkvT, g_wqkvT);
    cudaGetSymbolAddress((void**)&woutT, g_woutT);

    cudaFuncSetAttribute(gemm_f16,
                         cudaFuncAttributeMaxDynamicSharedMemorySize,
                         (int)GEMM_SMEM);
    cudaFuncSetAttribute(gemm_f16_m64,
                         cudaFuncAttributeMaxDynamicSharedMemorySize,
                         (int)GEMM64_SMEM);
    cudaFuncSetAttribute(attn_f16_kernel,
                         cudaFuncAttributeMaxDynamicSharedMemorySize,
                         (int)ATTN_SMEM);

    transpose_half_kernel<<<dim3(QKVW/32, DIM/32), 256>>>(wqkv, wqkvT, DIM, QKVW);
    transpose_half_kernel<<<dim3(DIM/32, INNER/32), 256>>>(wout, woutT, INNER, DIM);
    ln_kernel<<<ROWS/8, 256>>>(x, gamma, beta);
    gemm_f16<<<dim3(QKVW/128, ROWS/128), 128, GEMM_SMEM>>>(
        xn, wqkvT, qkv, ROWS, QKVW, DIM);
    attn_f16_kernel<<<dim3(BATCH, NSEQ/128, HEADS), 128, ATTN_SMEM>>>(bias);
    gemm_f16_m64<<<dim3(DIM/128, ROWS/64), 128, GEMM64_SMEM>>>(
        att, woutT, out, ROWS, DIM, INNER);
}